// round 17
// baseline (speedup 1.0000x reference)
#include <cuda_runtime.h>
#include <cstdint>

#define BB 64
#define CC 64
#define HH 128
#define WW 128
#define NSLAB (BB * CC)
#define GRID1 296   // persistent, single wave: 2/SM on 148 SMs (<=2/SM on 152).

// Scratch (allocation-free rule: __device__ globals)
__device__ float    g_cs_e [NSLAB * WW]; // colsum_e [b,c,w]  = sum_h exp(x-m)
__device__ float    g_cs_ey[NSLAB * WW]; // colsum_ey[b,c,w]  = sum_h exp(x-m)*wy[h]
__device__ unsigned g_done;              // monotonic CTA-completion counter

__device__ __forceinline__ void l2_prefetch_64k(const void* p) {
    asm volatile("cp.async.bulk.prefetch.L2.global [%0], %1;"
                 :: "l"(p), "r"(65536));
}

// L2 replacement policies (createpolicy + cache_hint: any width).
__device__ __forceinline__ uint64_t pol_evict_first() {
    uint64_t p;
    asm("createpolicy.fractional.L2::evict_first.b64 %0, 1.0;" : "=l"(p));
    return p;
}
__device__ __forceinline__ uint64_t pol_evict_last() {
    uint64_t p;
    asm("createpolicy.fractional.L2::evict_last.b64 %0, 1.0;" : "=l"(p));
    return p;
}

// x is single-use streaming data: demote its L2 lines.
__device__ __forceinline__ float4 ldg_evict_first(const float4* p, uint64_t pol) {
    float4 v;
    asm("ld.global.nc.L2::cache_hint.v4.f32 {%0,%1,%2,%3}, [%4], %5;"
        : "=f"(v.x), "=f"(v.y), "=f"(v.z), "=f"(v.w) : "l"(p), "l"(pol));
    return v;
}

// colsums are consumed by the epilogue: pin at the protected end of the LRU.
__device__ __forceinline__ void stg_evict_last(float* p, float v, uint64_t pol) {
    asm volatile("st.global.L2::cache_hint.f32 [%0], %1, %2;"
                 :: "l"(p), "f"(v), "l"(pol));
}

// ---- packed f32x2 helpers (Blackwell): halve fma-pipe issue in the hot loop.
__device__ __forceinline__ uint64_t pk2(float a, float b) {
    uint64_t r; asm("mov.b64 %0, {%1, %2};" : "=l"(r) : "f"(a), "f"(b)); return r;
}
__device__ __forceinline__ void upk2(uint64_t v, float& a, float& b) {
    asm("mov.b64 {%0, %1}, %2;" : "=f"(a), "=f"(b) : "l"(v));
}
__device__ __forceinline__ uint64_t mul2(uint64_t a, uint64_t b) {
    uint64_t r; asm("mul.rn.f32x2 %0, %1, %2;" : "=l"(r) : "l"(a), "l"(b)); return r;
}
__device__ __forceinline__ uint64_t add2(uint64_t a, uint64_t b) {
    uint64_t r; asm("add.rn.f32x2 %0, %1, %2;" : "=l"(r) : "l"(a), "l"(b)); return r;
}
__device__ __forceinline__ uint64_t fma2(uint64_t a, uint64_t b, uint64_t c) {
    uint64_t r; asm("fma.rn.f32x2 %0, %1, %2, %3;"
                    : "=l"(r) : "l"(a), "l"(b), "l"(c)); return r;
}
__device__ __forceinline__ float ex2f(float x) {
    float r; asm("ex2.approx.ftz.f32 %0, %1;" : "=f"(r) : "f"(x)); return r;
}

// ---------------------------------------------------------------------------
// Epilogue = the R12 measured-best pass2 body, run inline by CTAs 0..127.
// ---------------------------------------------------------------------------
__device__ __forceinline__ void epilogue(int blk, int tid, float* __restrict__ out) {
    const int b    = blk >> 1;
    const int half = blk & 1;

    const float* __restrict__ cse = g_cs_e  + (size_t)b * CC * WW;
    const float* __restrict__ csy = g_cs_ey + (size_t)b * CC * WW;

    __shared__ float sA[4][WW];
    __shared__ float rs[WW];

    const int w  = tid & 127;
    const int cg = tid >> 7;                    // 0..3
    float a[16];
#pragma unroll
    for (int k = 0; k < 16; k++)
        a[k] = cse[(cg + 4 * k) * WW + w];

    const int warp = tid >> 5;                  // 0..15
    const int lane = tid & 31;
    float pe[2][4], py[2][4];
#pragma unroll
    for (int i = 0; i < 2; i++) {
        const int c = half * 32 + warp * 2 + i;
#pragma unroll
        for (int j = 0; j < 4; j++) {
            const int ww = lane + 32 * j;
            pe[i][j] = cse[c * WW + ww];
            py[i][j] = csy[c * WW + ww];
        }
    }

    {
        float s = 0.f;
#pragma unroll
        for (int k = 0; k < 16; k++) s += a[k];
        sA[cg][w] = s;
    }
    __syncthreads();
    if (tid < WW)
        rs[tid] = 1.0f / (sA[0][tid] + sA[1][tid] + sA[2][tid] + sA[3][tid]);
    __syncthreads();

    const float inv127 = 1.0f / 127.0f;
#pragma unroll
    for (int i = 0; i < 2; i++) {
        const int c = half * 32 + warp * 2 + i;
        float xx = 0.f, xy = 0.f;
#pragma unroll
        for (int j = 0; j < 4; j++) {
            const int ww = lane + 32 * j;
            const float r = rs[ww];
            xx += pe[i][j] * ((float)ww * inv127) * r;
            xy += py[i][j] * r;
        }
#pragma unroll
        for (int o = 16; o; o >>= 1) {
            xx += __shfl_xor_sync(0xffffffffu, xx, o);
            xy += __shfl_xor_sync(0xffffffffu, xy, o);
        }
        if (lane == 0) {
            out[((size_t)b * CC + c) * 2 + 0] = xx;
            out[((size_t)b * CC + c) * 2 + 1] = xy;
        }
    }
}

// ---------------------------------------------------------------------------
// Fused persistent kernel — R15 structure exactly (41.4us best), with the
// inner accumulate switched to packed f32x2 math:
//   per float4: 4 FMNMX + 2 mul2 + 4 EX2 + 2 add2 + 2 fma2  (14 vs 20 slots).
// Accumulators stay packed across the slab; unpacked only at the combine.
// ---------------------------------------------------------------------------
__global__ __launch_bounds__(512, 2)
void sam_fused(const float* __restrict__ x, float* __restrict__ out) {
    const int tid = threadIdx.x;
    const int wg  = tid & 31;                   // w-group (4 consecutive floats)
    const int hs  = tid >> 5;                   // warp id == h subgroup 0..15

    __shared__ float  smax[2][16];
    __shared__ float4 se[2][16][32];            // [parity][warp][wg]
    __shared__ float4 sy[2][16][32];

    const float4* __restrict__ xp = reinterpret_cast<const float4*>(x);
    const float inv127 = 1.0f / 127.0f;
    const float L2E = 1.4426950408889634f;
    const uint64_t pf = pol_evict_first();
    const uint64_t pl = pol_evict_last();
    const uint64_t l2e2 = pk2(L2E, L2E);

    int bc = blockIdx.x;
    int p  = 0;
    if (tid == 0 && bc < NSLAB && bc + GRID1 < NSLAB)
        l2_prefetch_64k(xp + (size_t)(bc + GRID1) * (HH * WW / 4));

    for (; bc < NSLAB; bc += GRID1, p ^= 1) {
        if (tid == 0 && bc + 2 * GRID1 < NSLAB)
            l2_prefetch_64k(xp + (size_t)(bc + 2 * GRID1) * (HH * WW / 4));

        // ---- load (evict_first) + immediate packed exp-accumulate ----
        const float4* g = xp + (size_t)bc * (HH * WW / 4);
        float m = -1e30f;
        uint64_t ae01 = 0, ae23 = 0, ay01 = 0, ay23 = 0;   // packed (0.f,0.f)
#pragma unroll
        for (int r = 0; r < 8; r++) {
            float4 v = ldg_evict_first(&g[(hs + 16 * r) * (WW / 4) + wg], pf);
            m = fmaxf(m, fmaxf(fmaxf(v.x, v.y), fmaxf(v.z, v.w)));
            uint64_t t0 = mul2(pk2(v.x, v.y), l2e2);
            uint64_t t1 = mul2(pk2(v.z, v.w), l2e2);
            float a0, a1, a2, a3;
            upk2(t0, a0, a1); upk2(t1, a2, a3);
            uint64_t e01 = pk2(ex2f(a0), ex2f(a1));
            uint64_t e23 = pk2(ex2f(a2), ex2f(a3));
            const float wy = (float)(hs + 16 * r) * inv127;
            const uint64_t wy2 = pk2(wy, wy);
            ae01 = add2(ae01, e01);
            ae23 = add2(ae23, e23);
            ay01 = fma2(e01, wy2, ay01);
            ay23 = fma2(e23, wy2, ay23);
        }
        float ae0, ae1, ae2, ae3, ay0, ay1, ay2, ay3;
        upk2(ae01, ae0, ae1); upk2(ae23, ae2, ae3);
        upk2(ay01, ay0, ay1); upk2(ay23, ay2, ay3);

        // ---- warp max + publish partials ----
#pragma unroll
        for (int o = 16; o; o >>= 1)
            m = fmaxf(m, __shfl_xor_sync(0xffffffffu, m, o));
        if (wg == 0) smax[p][hs] = m;
        se[p][hs][wg] = make_float4(ae0, ae1, ae2, ae3);
        sy[p][hs][wg] = make_float4(ay0, ay1, ay2, ay3);
        __syncthreads();                        // single barrier per slab

        // ---- combine (tid<256); others run ahead into next slab's loads ----
        if (tid < 256) {
            float mc = smax[p][0];
#pragma unroll
            for (int k = 1; k < 16; k++) mc = fmaxf(mc, smax[p][k]);
            const float scale = ex2f(-mc * L2E);

            if (tid < 128) {
                const float* q = reinterpret_cast<const float*>(se[p]);
                float s = 0.f;
#pragma unroll
                for (int k = 0; k < 16; k++) s += q[k * 128 + tid];
                stg_evict_last(&g_cs_e[(size_t)bc * WW + tid], s * scale, pl);
            } else {
                const int w = tid - 128;
                const float* q = reinterpret_cast<const float*>(sy[p]);
                float s = 0.f;
#pragma unroll
                for (int k = 0; k < 16; k++) s += q[k * 128 + w];
                stg_evict_last(&g_cs_ey[(size_t)bc * WW + w], s * scale, pl);
            }
        }
    }

    // ---- grid-wide completion: one release + atomic per CTA ----
    __syncthreads();
    const int blk = blockIdx.x;
    if (tid == 0) {
        __threadfence();                        // release this CTA's colsums
        unsigned old = atomicAdd(&g_done, 1u);
        unsigned target = (old / GRID1 + 1u) * GRID1;   // this launch's 296th
        if (blk < 2 * BB) {
            volatile unsigned* vd = &g_done;
            while (*vd < target) __nanosleep(64);
            __threadfence();                    // acquire all CTAs' colsums
        }
    }
    if (blk >= 2 * BB) return;                  // uniform per CTA: safe
    __syncthreads();                            // all threads see completion

    epilogue(blk, tid, out);
}

extern "C" void kernel_launch(void* const* d_in, const int* in_sizes, int n_in,
                              void* d_out, int out_size) {
    const float* x = (const float*)d_in[0];
    float* out = (float*)d_out;
    sam_fused<<<GRID1, 512>>>(x, out);
}